// round 15
// baseline (speedup 1.0000x reference)
#include <cuda_runtime.h>
#include <cuda_bf16.h>

// LightplaneSplatter: splat N rays x 72 samples x 16 channels into a
// (1,128,128,128,16) grid with trilinear weights, masking OOB corners.
//
// R14: z-slab pipelining with ALL work on created (non-default) streams.
// R12/R13 failed to overlap because the main chain ran on the LEGACY default
// stream, which implicitly synchronizes with every other stream. Here:
//   capture stream: fork event -> ... -> join event
//   sA: zero_lo (planes [0,25)) -> splat_lo (bz<=23) -> wait eB -> splat_hi (bz>=24)
//   sB: zero_hi (planes [25,128)) -> eB
// zero_hi (~18us DRAM writes) overlaps zero_lo+splat_lo (~25us, LSU-bound).
// Lo slab kept small: split tax is ~4us/launch, so minimize serial zero_lo.
//
// Inputs (metadata order):
//   d_in[0] directions  float32 [N,3]
//   d_in[1] origins     float32 [N,3]
//   d_in[2] near        float32 [N]
//   d_in[3] far         float32 [N]
//   d_in[4] encoding    float32 [N,16]
//   d_in[5] grid_idx    int32   [N]
// Output: float32 grid [1,128,128,128,16] flattened (33,554,432 elems).

#define GW 128
#define GH 128
#define GD 128
#define GC 16
#define NUM_SAMPLES 64
#define NUM_SAMPLES_INF 8
#define ST (NUM_SAMPLES + NUM_SAMPLES_INF)  // 72
#define DISPARITY_AT_INF 1e-4f

// Strides in floats
#define SXs (GC)            // 16
#define SYs (GW * GC)       // 2048
#define SZs (GH * GW * GC)  // 262144

// Cell split: lo = cells bz in [-1, ZC-1], hi = cells bz in [ZC, 127].
// Lo cells touch vertex planes z <= ZC; hi cells touch z >= ZC.
// Plane ZC is zeroed in the lo region ([0, ZC+1)), so hi only needs
// planes [ZC+1, 128) zeroed before it runs.
#define ZC 24

__device__ __forceinline__ void red_add_v4(float* p, float x, float y, float z, float w) {
    asm volatile("red.global.add.v4.f32 [%0], {%1, %2, %3, %4};"
                 :: "l"(p), "f"(x), "f"(y), "f"(z), "f"(w)
                 : "memory");
}

// Grid-stride float4 zero kernel.
__global__ void zero_kernel(float4* __restrict__ p, long long n4)
{
    const float4 z = make_float4(0.f, 0.f, 0.f, 0.f);
    const long long stride = (long long)gridDim.x * blockDim.x;
    for (long long i = (long long)blockIdx.x * blockDim.x + threadIdx.x;
         i < n4; i += stride)
        p[i] = z;
}

// block: x = 4 channel-quads (float4 each), y = 72 samples -> 288 threads
// grid:  x = N rays. Emits only corners of cells with bz in [zlo, zhi].
__global__ void __launch_bounds__(288) splat_kernel(
    const float* __restrict__ dirs,
    const float* __restrict__ orig,
    const float* __restrict__ nearv,
    const float* __restrict__ farv,
    const float* __restrict__ enc,
    const int*   __restrict__ gidx,
    float* __restrict__ out,
    int zlo, int zhi)
{
    const int n  = blockIdx.x;
    const int si = threadIdx.y;   // 0..71
    const int c4 = threadIdx.x;   // 0..3

    const float nr = nearv[n];
    const float fr = farv[n];

    float t;
    if (si < NUM_SAMPLES) {
        t = nr + (fr - nr) * (((float)si + 0.5f) * (1.0f / NUM_SAMPLES));
    } else {
        const float j    = (float)(si - NUM_SAMPLES + 1) * (1.0f / NUM_SAMPLES_INF);
        const float invf = 1.0f / fr;
        const float disp = invf + (DISPARITY_AT_INF - invf) * j;
        t = 1.0f / disp;
    }

    const float px = orig[n * 3 + 0] + t * dirs[n * 3 + 0];
    const float py = orig[n * 3 + 1] + t * dirs[n * 3 + 1];
    const float pz = orig[n * 3 + 2] + t * dirs[n * 3 + 2];

    const float vx = (px + 1.0f) * 0.5f * (float)(GW - 1);
    const float vy = (py + 1.0f) * 0.5f * (float)(GH - 1);
    const float vz = (pz + 1.0f) * 0.5f * (float)(GD - 1);

    const float bxf = floorf(vx);
    const float byf = floorf(vy);
    const float bzf = floorf(vz);

    // Written so NaN also fails -> skip.
    const bool maybe_in =
        (bxf >= -1.0f) && (bxf <= (float)(GW - 1)) &&
        (byf >= -1.0f) && (byf <= (float)(GH - 1)) &&
        (bzf >= -1.0f) && (bzf <= (float)(GD - 1));
    if (!maybe_in) return;

    const int bz = (int)bzf;
    if (bz < zlo || bz > zhi) return;   // other slab's launch handles it

    const float fx = vx - bxf;
    const float fy = vy - byf;
    const float fz = vz - bzf;
    const int bx = (int)bxf;
    const int by = (int)byf;

    const float4 e = *reinterpret_cast<const float4*>(enc + n * GC + c4 * 4);
    const int   b = gidx[n];

    const float wx0 = 1.0f - fx, wx1 = fx;
    const float wy0 = 1.0f - fy, wy1 = fy;
    const float wz0 = 1.0f - fz, wz1 = fz;

    const bool x0 = (unsigned)bx       < GW;
    const bool x1 = (unsigned)(bx + 1) < GW;
    const bool y0 = (unsigned)by       < GH;
    const bool y1 = (unsigned)(by + 1) < GH;
    const bool z0 = (unsigned)bz       < GD;
    const bool z1 = (unsigned)(bz + 1) < GD;

    const long long basef =
        ((((long long)b * GD + bz) * GH + by) * GW + bx) * GC + c4 * 4;
    float* const pb = out + basef;

#pragma unroll
    for (int k = 0; k < 8; k++) {
        const int ddx = k & 1, ddy = (k >> 1) & 1, ddz = (k >> 2) & 1;
        const bool inb = (ddx ? x1 : x0) & (ddy ? y1 : y0) & (ddz ? z1 : z0);
        if (inb) {
            const float w = (ddx ? wx1 : wx0) * (ddy ? wy1 : wy0) * (ddz ? wz1 : wz0);
            red_add_v4(pb + (ddz * SZs + ddy * SYs + ddx * SXs),
                       w * e.x, w * e.y, w * e.z, w * e.w);
        }
    }
}

// Host-side aux objects, created at static-init time (host objects only;
// no device allocation anywhere).
namespace {
struct Aux {
    cudaStream_t sA = nullptr, sB = nullptr;
    cudaEvent_t  eFork = nullptr, eB = nullptr, eDone = nullptr;
    bool ok = false;
    Aux() {
        ok = (cudaStreamCreateWithFlags(&sA, cudaStreamNonBlocking) == cudaSuccess)
          && (cudaStreamCreateWithFlags(&sB, cudaStreamNonBlocking) == cudaSuccess)
          && (cudaEventCreateWithFlags(&eFork, cudaEventDisableTiming) == cudaSuccess)
          && (cudaEventCreateWithFlags(&eB,    cudaEventDisableTiming) == cudaSuccess)
          && (cudaEventCreateWithFlags(&eDone, cudaEventDisableTiming) == cudaSuccess);
    }
};
Aux g_aux;
}  // namespace

extern "C" void kernel_launch(void* const* d_in, const int* in_sizes, int n_in,
                              void* d_out, int out_size)
{
    const float* dirs  = (const float*)d_in[0];
    const float* orig  = (const float*)d_in[1];
    const float* nearv = (const float*)d_in[2];
    const float* farv  = (const float*)d_in[3];
    const float* enc   = (const float*)d_in[4];
    const int*   gidx  = (const int*)  d_in[5];
    float* out = (float*)d_out;

    const int N = in_sizes[2];  // near has one element per ray

    dim3 block(4, ST, 1);
    dim3 grid(N, 1, 1);

    if (g_aux.ok) {
        const long long lo_floats = (long long)(ZC + 1) * SZs;   // planes [0, ZC+1)
        const long long hi_floats = (long long)out_size - lo_floats;

        // Fork from the capture stream; NO kernels on the legacy default
        // stream (it implicitly serializes with all other streams).
        cudaEventRecord(g_aux.eFork, 0);
        cudaStreamWaitEvent(g_aux.sA, g_aux.eFork, 0);
        cudaStreamWaitEvent(g_aux.sB, g_aux.eFork, 0);

        // sB: zero the hi planes [ZC+1, 128)  (overlaps sA's zero_lo+splat_lo)
        zero_kernel<<<2048, 256, 0, g_aux.sB>>>(
            (float4*)(out + lo_floats), hi_floats / 4);
        cudaEventRecord(g_aux.eB, g_aux.sB);

        // sA: zero lo planes, splat lo cells (bz <= ZC-1 -> vertices z <= ZC)
        zero_kernel<<<2048, 256, 0, g_aux.sA>>>((float4*)out, lo_floats / 4);
        splat_kernel<<<grid, block, 0, g_aux.sA>>>(
            dirs, orig, nearv, farv, enc, gidx, out, -1, ZC - 1);

        // sA: wait for hi zeroing, then splat hi cells (bz >= ZC)
        cudaStreamWaitEvent(g_aux.sA, g_aux.eB, 0);
        splat_kernel<<<grid, block, 0, g_aux.sA>>>(
            dirs, orig, nearv, farv, enc, gidx, out, ZC, GD - 1);

        // Join back to the capture stream.
        cudaEventRecord(g_aux.eDone, g_aux.sA);
        cudaStreamWaitEvent(0, g_aux.eDone, 0);
    } else {
        // Fallback: serial path (identical to best prior kernel).
        zero_kernel<<<2048, 256>>>((float4*)out, (long long)out_size / 4);
        splat_kernel<<<grid, block>>>(dirs, orig, nearv, farv, enc, gidx, out,
                                      -1, GD - 1);
    }
}